// round 9
// baseline (speedup 1.0000x reference)
#include <cuda_runtime.h>
#include <cuda_bf16.h>
#include <math.h>
#include <math_constants.h>
#include <stdint.h>

#define HIDDEN 2048
#define NH 16
#define NKV 4
#define HD 128
#define KVD 512
#define BATCH 2
#define SEQ 2048
#define M_TOT (BATCH * SEQ)   // 4096

// ---------------- scratch (no allocations allowed) ----------------
__device__ float g_q[M_TOT * HIDDEN];
__device__ float g_k[M_TOT * KVD];
__device__ float g_v[M_TOT * KVD];
__device__ float g_cos[SEQ * 64];
__device__ float g_sin[SEQ * 64];
// bf16 hi/lo split arrays
__device__ __nv_bfloat16 g_hsh[M_TOT * HIDDEN],  g_hsl[M_TOT * HIDDEN];
__device__ __nv_bfloat16 g_wqh[HIDDEN * HIDDEN], g_wql[HIDDEN * HIDDEN];
__device__ __nv_bfloat16 g_wkh[KVD * HIDDEN],    g_wkl[KVD * HIDDEN];
__device__ __nv_bfloat16 g_wvh[KVD * HIDDEN],    g_wvl[KVD * HIDDEN];
__device__ __nv_bfloat16 g_woh[HIDDEN * HIDDEN], g_wol[HIDDEN * HIDDEN];
__device__ __nv_bfloat16 g_qh[M_TOT * HIDDEN],   g_ql[M_TOT * HIDDEN];
__device__ __nv_bfloat16 g_kh[M_TOT * KVD],      g_kl[M_TOT * KVD];
__device__ __nv_bfloat16 g_vth[M_TOT * KVD],     g_vtl[M_TOT * KVD];  // [b][kvh][d][s]
__device__ __nv_bfloat16 g_ch[M_TOT * HIDDEN],   g_cl[M_TOT * HIDDEN];

// ---------------- helpers ----------------
__device__ __forceinline__ void split_bf16(float x, __nv_bfloat16& h, __nv_bfloat16& l) {
    h = __float2bfloat16_rn(x);
    l = __float2bfloat16_rn(x - __bfloat162float(h));
}
__device__ __forceinline__ uint32_t pack2(__nv_bfloat16 a, __nv_bfloat16 b) {
    __nv_bfloat162 t; t.x = a; t.y = b;   // low half = a (elem even)
    return *(uint32_t*)&t;
}
__device__ __forceinline__ void mma_bf16(float c[4], const uint32_t a[4], const uint32_t b[2]) {
    asm volatile(
        "mma.sync.aligned.m16n8k16.row.col.f32.bf16.bf16.f32 "
        "{%0,%1,%2,%3}, {%4,%5,%6,%7}, {%8,%9}, {%0,%1,%2,%3};"
        : "+f"(c[0]), "+f"(c[1]), "+f"(c[2]), "+f"(c[3])
        : "r"(a[0]), "r"(a[1]), "r"(a[2]), "r"(a[3]), "r"(b[0]), "r"(b[1]));
}
#define CP_ASYNC16(sm32, gp) \
    asm volatile("cp.async.cg.shared.global [%0], [%1], 16;" :: "r"(sm32), "l"(gp))
#define CP_COMMIT() asm volatile("cp.async.commit_group;" ::: "memory")
#define CP_WAIT0()  asm volatile("cp.async.wait_group 0;" ::: "memory")
#define CP_WAIT1()  asm volatile("cp.async.wait_group 1;" ::: "memory")
#define CP_WAIT2()  asm volatile("cp.async.wait_group 2;" ::: "memory")

// ---------------- prep kernels ----------------
__global__ void rope_table_kernel() {
    int i = blockIdx.x * blockDim.x + threadIdx.x;
    if (i >= SEQ * 64) return;
    int pos = i / 64, j = i % 64;
    double inv = exp(-((double)(2 * j) / (double)HD) * log(10000.0));
    double ang = (double)pos * inv;
    g_cos[i] = (float)cos(ang);
    g_sin[i] = (float)sin(ang);
}

__global__ void split_kernel(const float* __restrict__ x,
                             __nv_bfloat16* __restrict__ h,
                             __nv_bfloat16* __restrict__ l, int n) {
    int i = blockIdx.x * blockDim.x + threadIdx.x;
    if (i >= n) return;
    __nv_bfloat16 hb, lb;
    split_bf16(x[i], hb, lb);
    h[i] = hb; l[i] = lb;
}

// RoPE + split: reads fp32 x, writes rotated hi/lo (same layout)
__global__ void rope_split_kernel(const float* __restrict__ x,
                                  __nv_bfloat16* __restrict__ xh,
                                  __nv_bfloat16* __restrict__ xl,
                                  int nheads, int total) {
    int i = blockIdx.x * blockDim.x + threadIdx.x;
    if (i >= total) return;
    int j = i % 64;
    int hh = (i / 64) % nheads;
    int m = i / (64 * nheads);
    int s = m % SEQ;
    float c = g_cos[s * 64 + j];
    float sn = g_sin[s * 64 + j];
    size_t base = (size_t)m * (nheads * HD) + hh * HD;
    float x0 = x[base + j];
    float x1 = x[base + j + 64];
    float y0 = x0 * c - x1 * sn;
    float y1 = x1 * c + x0 * sn;
    __nv_bfloat16 hb, lb;
    split_bf16(y0, hb, lb); xh[base + j] = hb;      xl[base + j] = lb;
    split_bf16(y1, hb, lb); xh[base + j + 64] = hb; xl[base + j + 64] = lb;
}

// V transpose + split: [m][KVD] fp32 -> [b][kvh][d][s] bf16 hi/lo
__global__ void vt_split_kernel(const float* __restrict__ v) {
    int i = blockIdx.x * blockDim.x + threadIdx.x;
    if (i >= M_TOT * KVD) return;
    int m = i / KVD, c = i % KVD;
    int b = m / SEQ, s = m % SEQ;
    int kvh = c / HD, d = c % HD;
    size_t o = (((size_t)(b * NKV + kvh)) * HD + d) * SEQ + s;
    __nv_bfloat16 hb, lb;
    split_bf16(v[i], hb, lb);
    g_vth[o] = hb; g_vtl[o] = lb;
}

// ============ bf16-split tensor GEMM (NT): C = (Ah+Al)(Bh+Bl)^T ============
// A:[M][K], B:[N][K] hi/lo bf16. CTA tile 128x128, BK=32; 128 thr = 4 warps
// in 2(m) x 2(n), warp tile 64x64 (mt=4, nt=8): smem frag traffic per FLOP
// is 2/3 of the 8-warp 64x32 layout (64 LDS ops per 96 HMMA vs 48 per 48).
// mma m16n8k16, 3 products (hh, hl, lh), fp32 accum. cp.async double-buffered.
#define GSA 20                       // row stride u32 (16 data + 4 pad): bank 4g+tig -> conflict-free
#define GTILE (128 * GSA)            // u32 per matrix tile
#define GBUF (4 * GTILE)             // Ah,Al,Bh,Bl
#define GEMM_SMEM (2 * GBUF * 4)     // double-buffered = 81920 B

__global__ void __launch_bounds__(128, 2) gemm_bf16_nt(
    const __nv_bfloat16* __restrict__ Ah, const __nv_bfloat16* __restrict__ Al,
    const __nv_bfloat16* __restrict__ Bh, const __nv_bfloat16* __restrict__ Bl,
    float* __restrict__ C, int Ndim, int Kdim)
{
    extern __shared__ uint32_t smu[];
    const int tid = threadIdx.x;
    const int wid = tid >> 5, lane = tid & 31;
    const int g = lane >> 2, tig = lane & 3;
    const int wm = wid & 1, wn = wid >> 1;     // 2x2 warp grid, 64x64 tiles
    const int bm0 = blockIdx.y * 128, bn0 = blockIdx.x * 128;
    const uint32_t smb = (uint32_t)__cvta_generic_to_shared(smu);
    const __nv_bfloat16* gp[4] = {Ah, Al, Bh, Bl};

    // loader: 4 float4 slots per matrix per thread (128 thr x 4 = 512 = 128 rows x 4)
    int rowL[4], q4L[4];
#pragma unroll
    for (int s = 0; s < 4; s++) {
        int f = tid + 128 * s;       // 0..511
        rowL[s] = f >> 2;            // 4 float4 per 16-u32 row
        q4L[s]  = f & 3;
    }

    float acc[4][8][4];
#pragma unroll
    for (int mt = 0; mt < 4; mt++)
#pragma unroll
        for (int nt = 0; nt < 8; nt++)
#pragma unroll
            for (int r = 0; r < 4; r++) acc[mt][nt][r] = 0.f;

    // prefetch tile 0 into buffer 0
#pragma unroll
    for (int mi = 0; mi < 4; mi++)
#pragma unroll
        for (int s = 0; s < 4; s++) {
            int row = rowL[s], q4 = q4L[s];
            int gbase = (mi < 2 ? bm0 : bn0);
            CP_ASYNC16(smb + (uint32_t)((mi * GTILE + row * GSA + q4 * 4) * 4),
                       gp[mi] + (size_t)(gbase + row) * Kdim + q4 * 8);
        }
    CP_COMMIT();

    int buf = 0;
    for (int k0 = 0; k0 < Kdim; k0 += 32) {
        CP_WAIT0();
        __syncthreads();

        if (k0 + 32 < Kdim) {
            uint32_t bb = smb + (uint32_t)(((buf ^ 1) * GBUF) * 4);
#pragma unroll
            for (int mi = 0; mi < 4; mi++)
#pragma unroll
                for (int s = 0; s < 4; s++) {
                    int row = rowL[s], q4 = q4L[s];
                    int gbase = (mi < 2 ? bm0 : bn0);
                    CP_ASYNC16(bb + (uint32_t)((mi * GTILE + row * GSA + q4 * 4) * 4),
                               gp[mi] + (size_t)(gbase + row) * Kdim + k0 + 32 + q4 * 8);
                }
        }
        CP_COMMIT();

        const uint32_t* Ash = smu + buf * GBUF;
        const uint32_t* Asl = Ash + GTILE;
        const uint32_t* Bsh = Ash + 2 * GTILE;
        const uint32_t* Bsl = Ash + 3 * GTILE;

#pragma unroll
        for (int ks = 0; ks < 2; ks++) {
            const int c = ks * 8 + tig;
            uint32_t ah[4][4], al[4][4];
#pragma unroll
            for (int mt = 0; mt < 4; mt++) {
                int row = wm * 64 + mt * 16 + g;
                ah[mt][0] = Ash[row * GSA + c];       ah[mt][1] = Ash[(row + 8) * GSA + c];
                ah[mt][2] = Ash[row * GSA + c + 4];   ah[mt][3] = Ash[(row + 8) * GSA + c + 4];
                al[mt][0] = Asl[row * GSA + c];       al[mt][1] = Asl[(row + 8) * GSA + c];
                al[mt][2] = Asl[row * GSA + c + 4];   al[mt][3] = Asl[(row + 8) * GSA + c + 4];
            }
#pragma unroll
            for (int nt = 0; nt < 8; nt++) {
                int n = wn * 64 + nt * 8 + g;
                uint32_t bh[2] = { Bsh[n * GSA + c], Bsh[n * GSA + c + 4] };
                uint32_t bl[2] = { Bsl[n * GSA + c], Bsl[n * GSA + c + 4] };
#pragma unroll
                for (int mt = 0; mt < 4; mt++) {
                    mma_bf16(acc[mt][nt], ah[mt], bh);
                    mma_bf16(acc[mt][nt], ah[mt], bl);
                    mma_bf16(acc[mt][nt], al[mt], bh);
                }
            }
        }
        buf ^= 1;
    }

#pragma unroll
    for (int mt = 0; mt < 4; mt++)
#pragma unroll
        for (int nt = 0; nt < 8; nt++) {
            int row = bm0 + wm * 64 + mt * 16 + g;
            int col = bn0 + wn * 64 + nt * 8 + 2 * tig;
            *(float2*)&C[(size_t)row * Ndim + col] =
                make_float2(acc[mt][nt][0], acc[mt][nt][1]);
            *(float2*)&C[(size_t)(row + 8) * Ndim + col] =
                make_float2(acc[mt][nt][2], acc[mt][nt][3]);
        }
}

// ============ bf16-split flash attention (causal, GQA) ============
// 128 q-rows per CTA, 64-wide kv tiles. 8 warps in 4(m) x 2(n):
// Scores warp tile 32x32 (mt=2, nt=4); PV warp tile 32x64 (mt=2, nt=8).
// K double-buffered cp.async; V^T deferred-wait; fp32 score staging
// aliased onto the consumed K buffer. P split to bf16 hi/lo in softmax.
#define FBM 128
#define FBN 64
#define QS 68   // u32 row stride (64 data + 4 pad): 4g+tig conflict-free
#define KS 68
#define VS 36   // 32 data + 4
#define PS 36
#define OQH 0
#define OQL 8704
#define OKH0 17408
#define OKL0 21760
#define OKH1 26112
#define OKL1 30464
#define OVTH 34816
#define OVTL 39424
#define OPH 44032
#define OPL 48640
#define OSROW 53248
#define OAMS 53376
#define FLASH_SMEM (53440 * 4)

__global__ void __launch_bounds__(256, 1) flash_bf16(const int* __restrict__ am) {
    extern __shared__ uint32_t smu[];
    float* srow = (float*)(smu + OSROW);
    int* ams = (int*)(smu + OAMS);

    const int tid = threadIdx.x;
    const int wid = tid >> 5, lane = tid & 31;
    const int g = lane >> 2, tig = lane & 3;
    const int wm = wid & 3, wn = wid >> 2;     // 4m x 2n
    const int qt = blockIdx.x, hh = blockIdx.y, b = blockIdx.z;
    const int q0 = qt * FBM;
    const int kvh = hh / (NH / NKV);
    const int tx = tid & 15, ty = tid >> 4;
    const uint32_t smb = (uint32_t)__cvta_generic_to_shared(smu);

    // ---- prologue: Q (hi+lo) + K(0) via cp.async, one group ----
    {
        const __nv_bfloat16* qhp = g_qh + ((size_t)(b * SEQ + q0) * HIDDEN + hh * HD);
        const __nv_bfloat16* qlp = g_ql + ((size_t)(b * SEQ + q0) * HIDDEN + hh * HD);
#pragma unroll
        for (int i = 0; i < 8; i++) {
            int c = tid + 256 * i, row = c >> 4, o = c & 15;
            CP_ASYNC16(smb + (uint32_t)((OQH + row * QS + o * 4) * 4), qhp + (size_t)row * HIDDEN + o * 8);
            CP_ASYNC16(smb + (uint32_t)((OQL + row * QS + o * 4) * 4), qlp + (size_t)row * HIDDEN + o * 8);
        }
        const __nv_bfloat16* khp = g_kh + ((size_t)(b * SEQ) * KVD + kvh * HD);
        const __nv_bfloat16* klp = g_kl + ((size_t)(b * SEQ) * KVD + kvh * HD);
#pragma unroll
        for (int i = 0; i < 4; i++) {
            int c = tid + 256 * i, row = c >> 4, o = c & 15;
            CP_ASYNC16(smb + (uint32_t)((OKH0 + row * KS + o * 4) * 4), khp + (size_t)row * KVD + o * 8);
            CP_ASYNC16(smb + (uint32_t)((OKL0 + row * KS + o * 4) * 4), klp + (size_t)row * KVD + o * 8);
        }
        CP_COMMIT();
    }

    float acc[2][8][4];     // PV accum: mt=2 (rows wm*32+mt*16+g,+8), nt=8 (d cols)
#pragma unroll
    for (int mt = 0; mt < 2; mt++)
#pragma unroll
        for (int nt = 0; nt < 8; nt++)
#pragma unroll
            for (int r = 0; r < 4; r++) acc[mt][nt][r] = 0.f;
    float mrow[8], lrow[8];
#pragma unroll
    for (int i = 0; i < 8; i++) { mrow[i] = -CUDART_INF_F; lrow[i] = 0.f; }

    const int nkt = q0 / FBN + 2;
    int buf = 0;
    for (int kt = 0; kt < nkt; kt++) {
        const int k0 = kt * FBN;
        __syncthreads();   // PV(t-1) done with VT/P; Sraw(t-1) consumed

        // V^T(t) group
        {
            const __nv_bfloat16* vhp = g_vth + ((size_t)(b * NKV + kvh) * HD) * SEQ;
            const __nv_bfloat16* vlp = g_vtl + ((size_t)(b * NKV + kvh) * HD) * SEQ;
#pragma unroll
            for (int i = 0; i < 4; i++) {
                int c = tid + 256 * i, d = c >> 3, o = c & 7;
                CP_ASYNC16(smb + (uint32_t)((OVTH + d * VS + o * 4) * 4), vhp + (size_t)d * SEQ + k0 + o * 8);
                CP_ASYNC16(smb + (uint32_t)((OVTL + d * VS + o * 4) * 4), vlp + (size_t)d * SEQ + k0 + o * 8);
            }
            CP_COMMIT();
        }
        // K(t+1) group into other buffer (committed even if empty)
        if (kt + 1 < nkt) {
            int okh = buf ? OKH0 : OKH1;
            int okl = buf ? OKL0 : OKL1;
            const __nv_bfloat16* khp = g_kh + ((size_t)(b * SEQ + k0 + FBN) * KVD + kvh * HD);
            const __nv_bfloat16* klp = g_kl + ((size_t)(b * SEQ + k0 + FBN) * KVD + kvh * HD);
#pragma unroll
            for (int i = 0; i < 4; i++) {
                int c = tid + 256 * i, row = c >> 4, o = c & 15;
                CP_ASYNC16(smb + (uint32_t)((okh + row * KS + o * 4) * 4), khp + (size_t)row * KVD + o * 8);
                CP_ASYNC16(smb + (uint32_t)((okl + row * KS + o * 4) * 4), klp + (size_t)row * KVD + o * 8);
            }
        }
        CP_COMMIT();

        if (tid < FBN) ams[tid] = am[b * SEQ + k0 + tid];

        CP_WAIT2();        // K(t) (and Q) complete
        __syncthreads();

        const uint32_t* Kh = smu + (buf ? OKH1 : OKH0);
        const uint32_t* Kl = smu + (buf ? OKL1 : OKL0);
        const uint32_t* Qh = smu + OQH;
        const uint32_t* Ql = smu + OQL;

        // ---- scores: S = (Qh+Ql)(Kh+Kl)^T, warp tile 32x32 ----
        float accs[2][4][4];
#pragma unroll
        for (int mt = 0; mt < 2; mt++)
#pragma unroll
            for (int nt = 0; nt < 4; nt++)
#pragma unroll
                for (int r = 0; r < 4; r++) accs[mt][nt][r] = 0.f;

#pragma unroll
        for (int ks = 0; ks < 8; ks++) {
            const int c = ks * 8 + tig;
            uint32_t ah[2][4], al[2][4];
#pragma unroll
            for (int mt = 0; mt < 2; mt++) {
                int row = wm * 32 + mt * 16 + g;
                ah[mt][0] = Qh[row * QS + c];     ah[mt][1] = Qh[(row + 8) * QS + c];
                ah[mt][2] = Qh[row * QS + c + 4]; ah[mt][3] = Qh[(row + 8) * QS + c + 4];
                al[mt][0] = Ql[row * QS + c];     al[mt][1] = Ql[(row + 8) * QS + c];
                al[mt][2] = Ql[row * QS + c + 4]; al[mt][3] = Ql[(row + 8) * QS + c + 4];
            }
#pragma unroll
            for (int nt = 0; nt < 4; nt++) {
                int n = wn * 32 + nt * 8 + g;
                uint32_t bh[2] = { Kh[n * KS + c], Kh[n * KS + c + 4] };
                uint32_t bl[2] = { Kl[n * KS + c], Kl[n * KS + c + 4] };
#pragma unroll
                for (int mt = 0; mt < 2; mt++) {
                    mma_bf16(accs[mt][nt], ah[mt], bh);
                    mma_bf16(accs[mt][nt], ah[mt], bl);
                    mma_bf16(accs[mt][nt], al[mt], bh);
                }
            }
        }
        __syncthreads();   // ALL warps done reading K(t) before aliasing

        // ---- stage raw scores fp32 into the consumed K buffer ----
        float* Sraw = (float*)(smu + (buf ? OKH1 : OKH0));   // [128][68]
#pragma unroll
        for (int mt = 0; mt < 2; mt++)
#pragma unroll
            for (int nt = 0; nt < 4; nt++) {
                int r0 = wm * 32 + mt * 16 + g;
                int c0 = wn * 32 + nt * 8 + 2 * tig;
                *(float2*)&Sraw[r0 * 68 + c0]       = make_float2(accs[mt][nt][0], accs[mt][nt][1]);
                *(float2*)&Sraw[(r0 + 8) * 68 + c0] = make_float2(accs[mt][nt][2], accs[mt][nt][3]);
            }
        __syncthreads();

        // ---- softmax: scale+mask, online rescale, write P hi/lo bf16 ----
        const float scale = 0.08838834764831845f;  // 1/sqrt(128)
#pragma unroll
        for (int i = 0; i < 8; i++) {
            int row = ty * 8 + i;
            int qglob = q0 + row;
            float4 s = *(float4*)&Sraw[row * 68 + tx * 4];
            float sv[4] = {s.x, s.y, s.z, s.w};
#pragma unroll
            for (int j = 0; j < 4; j++) {
                int kg = k0 + tx * 4 + j;
                float v = sv[j] * scale + ((ams[tx * 4 + j] == 0) ? -CUDART_INF_F : 0.f);
                if (kg > qglob) v = -CUDART_INF_F;
                sv[j] = v;
            }
            float mloc = fmaxf(fmaxf(sv[0], sv[1]), fmaxf(sv[2], sv[3]));
#pragma unroll
            for (int o = 8; o >= 1; o >>= 1)
                mloc = fmaxf(mloc, __shfl_xor_sync(0xffffffffu, mloc, o));
            float mnew = fmaxf(mrow[i], mloc);
            float alpha = __expf(mrow[i] - mnew);
            float p[4];
            float ls = 0.f;
#pragma unroll
            for (int j = 0; j < 4; j++) { p[j] = __expf(sv[j] - mnew); ls += p[j]; }
#pragma unroll
            for (int o = 8; o >= 1; o >>= 1)
                ls += __shfl_xor_sync(0xffffffffu, ls, o);
            lrow[i] = lrow[i] * alpha + ls;
            mrow[i] = mnew;
            __nv_bfloat16 h0, l0, h1, l1, h2, l2, h3, l3;
            split_bf16(p[0], h0, l0); split_bf16(p[1], h1, l1);
            split_bf16(p[2], h2, l2); split_bf16(p[3], h3, l3);
            smu[OPH + row * PS + 2 * tx]     = pack2(h0, h1);
            smu[OPH + row * PS + 2 * tx + 1] = pack2(h2, h3);
            smu[OPL + row * PS + 2 * tx]     = pack2(l0, l1);
            smu[OPL + row * PS + 2 * tx + 1] = pack2(l2, l3);
            if (tx == 0) srow[row] = alpha;
        }

        CP_WAIT1();        // V^T(t) complete (only K(t+1) may remain)
        __syncthreads();   // P, srow, V^T visible to all

        // ---- PV: acc = acc*alpha + (Ph+Pl)(Vh+Vl), warp tile 32x64 ----
#pragma unroll
        for (int mt = 0; mt < 2; mt++) {
            int r0 = wm * 32 + mt * 16 + g;
            float a0 = srow[r0], a1 = srow[r0 + 8];
#pragma unroll
            for (int nt = 0; nt < 8; nt++) {
                acc[mt][nt][0] *= a0; acc[mt][nt][1] *= a0;
                acc[mt][nt][2] *= a1; acc[mt][nt][3] *= a1;
            }
        }
        const uint32_t* Ph = smu + OPH;
        const uint32_t* Pl = smu + OPL;
        const uint32_t* Vh = smu + OVTH;
        const uint32_t* Vl = smu + OVTL;
#pragma unroll
        for (int ks = 0; ks < 4; ks++) {
            const int c = ks * 8 + tig;
            uint32_t ah[2][4], al[2][4];
#pragma unroll
            for (int mt = 0; mt < 2; mt++) {
                int row = wm * 32 + mt * 16 + g;
                ah[mt][0] = Ph[row * PS + c];     ah[mt][1] = Ph[(row + 8) * PS + c];
                ah[mt][2] = Ph[row * PS + c + 4]; ah[mt][3] = Ph[(row + 8) * PS + c + 4];
                al[mt][0] = Pl[row * PS + c];     al[mt][1] = Pl[(row + 8) * PS + c];
                al[mt][2] = Pl[row * PS + c + 4]; al[mt][3] = Pl[(row + 8) * PS + c + 4];
            }
#pragma unroll
            for (int nt = 0; nt < 8; nt++) {
                int d0 = wn * 64 + nt * 8 + g;
                uint32_t bh[2] = { Vh[d0 * VS + c], Vh[d0 * VS + c + 4] };
                uint32_t bl[2] = { Vl[d0 * VS + c], Vl[d0 * VS + c + 4] };
#pragma unroll
                for (int mt = 0; mt < 2; mt++) {
                    mma_bf16(acc[mt][nt], ah[mt], bh);
                    mma_bf16(acc[mt][nt], ah[mt], bl);
                    mma_bf16(acc[mt][nt], al[mt], bh);
                }
            }
        }
        buf ^= 1;
    }

    // ---- finalize: 1/l, write ctx hi/lo bf16 ----
    __syncthreads();
#pragma unroll
    for (int i = 0; i < 8; i++)
        if (tx == 0) srow[ty * 8 + i] = 1.0f / lrow[i];
    __syncthreads();

#pragma unroll
    for (int mt = 0; mt < 2; mt++) {
        int r0 = wm * 32 + mt * 16 + g;
        float inv0 = srow[r0], inv1 = srow[r0 + 8];
#pragma unroll
        for (int nt = 0; nt < 8; nt++) {
            int col = hh * HD + wn * 64 + nt * 8 + 2 * tig;
            size_t m0 = (size_t)(b * SEQ + q0 + r0) * HIDDEN + col;
            size_t m1 = (size_t)(b * SEQ + q0 + r0 + 8) * HIDDEN + col;
            __nv_bfloat16 h0, l0, h1, l1;
            split_bf16(acc[mt][nt][0] * inv0, h0, l0);
            split_bf16(acc[mt][nt][1] * inv0, h1, l1);
            *(uint32_t*)&g_ch[m0] = pack2(h0, h1);
            *(uint32_t*)&g_cl[m0] = pack2(l0, l1);
            split_bf16(acc[mt][nt][2] * inv1, h0, l0);
            split_bf16(acc[mt][nt][3] * inv1, h1, l1);
            *(uint32_t*)&g_ch[m1] = pack2(h0, h1);
            *(uint32_t*)&g_cl[m1] = pack2(l0, l1);
        }
    }
}

// ---------------- launch ----------------
extern "C" void kernel_launch(void* const* d_in, const int* in_sizes, int n_in,
                              void* d_out, int out_size) {
    (void)in_sizes; (void)n_in; (void)out_size;
    const float* hs = (const float*)d_in[0];
    const int*   am = (const int*)d_in[1];
    const float* wq = (const float*)d_in[2];
    const float* wk = (const float*)d_in[3];
    const float* wv = (const float*)d_in[4];
    const float* wo = (const float*)d_in[5];
    float* out = (float*)d_out;

    float *q, *k, *v;
    __nv_bfloat16 *hsh, *hsl, *wqh, *wql, *wkh, *wkl, *wvh, *wvl, *woh, *wol;
    __nv_bfloat16 *qh, *ql, *kh, *kl, *ch, *cl;
    cudaGetSymbolAddress((void**)&q, g_q);
    cudaGetSymbolAddress((void**)&k, g_k);
    cudaGetSymbolAddress((void**)&v, g_v);
    cudaGetSymbolAddress((void**)&hsh, g_hsh); cudaGetSymbolAddress((void**)&hsl, g_hsl);
    cudaGetSymbolAddress((void**)&wqh, g_wqh); cudaGetSymbolAddress((void**)&wql, g_wql);
    cudaGetSymbolAddress((void**)&wkh, g_wkh); cudaGetSymbolAddress((void**)&wkl, g_wkl);
    cudaGetSymbolAddress((void**)&wvh, g_wvh); cudaGetSymbolAddress((void**)&wvl, g_wvl);
    cudaGetSymbolAddress((void**)&woh, g_woh); cudaGetSymbolAddress((void**)&wol, g_wol);
    cudaGetSymbolAddress((void**)&qh, g_qh);   cudaGetSymbolAddress((void**)&ql, g_ql);
    cudaGetSymbolAddress((void**)&kh, g_kh);   cudaGetSymbolAddress((void**)&kl, g_kl);
    cudaGetSymbolAddress((void**)&ch, g_ch);   cudaGetSymbolAddress((void**)&cl, g_cl);

    cudaFuncSetAttribute(gemm_bf16_nt,
                         cudaFuncAttributeMaxDynamicSharedMemorySize, GEMM_SMEM);
    cudaFuncSetAttribute(flash_bf16,
                         cudaFuncAttributeMaxDynamicSharedMemorySize, FLASH_SMEM);

    rope_table_kernel<<<(SEQ * 64 + 255) / 256, 256>>>();

    // split inputs/weights
    split_kernel<<<(M_TOT * HIDDEN + 255) / 256, 256>>>(hs, hsh, hsl, M_TOT * HIDDEN);
    split_kernel<<<(HIDDEN * HIDDEN + 255) / 256, 256>>>(wq, wqh, wql, HIDDEN * HIDDEN);
    split_kernel<<<(KVD * HIDDEN + 255) / 256, 256>>>(wk, wkh, wkl, KVD * HIDDEN);
    split_kernel<<<(KVD * HIDDEN + 255) / 256, 256>>>(wv, wvh, wvl, KVD * HIDDEN);
    split_kernel<<<(HIDDEN * HIDDEN + 255) / 256, 256>>>(wo, woh, wol, HIDDEN * HIDDEN);

    // projections (4-warp, 64x64 warp-tile GEMM)
    gemm_bf16_nt<<<dim3(HIDDEN / 128, M_TOT / 128), 128, GEMM_SMEM>>>(hsh, hsl, wqh, wql, q, HIDDEN, HIDDEN);
    gemm_bf16_nt<<<dim3(KVD / 128,   M_TOT / 128), 128, GEMM_SMEM>>>(hsh, hsl, wkh, wkl, k, KVD, HIDDEN);
    gemm_bf16_nt<<<dim3(KVD / 128,   M_TOT / 128), 128, GEMM_SMEM>>>(hsh, hsl, wvh, wvl, v, KVD, HIDDEN);

    // rope + split q/k; transpose + split v
    rope_split_kernel<<<(M_TOT * NH * 64 + 255) / 256, 256>>>(q, qh, ql, NH, M_TOT * NH * 64);
    rope_split_kernel<<<(M_TOT * NKV * 64 + 255) / 256, 256>>>(k, kh, kl, NKV, M_TOT * NKV * 64);
    vt_split_kernel<<<(M_TOT * KVD + 255) / 256, 256>>>(v);

    // attention
    flash_bf16<<<dim3(SEQ / FBM, NH, BATCH), 256, FLASH_SMEM>>>(am);

    // output projection
    gemm_bf16_nt<<<dim3(HIDDEN / 128, M_TOT / 128), 128, GEMM_SMEM>>>(ch, cl, woh, wol, out, HIDDEN, HIDDEN);
}

// round 12
// speedup vs baseline: 1.0693x; 1.0693x over previous
#include <cuda_runtime.h>
#include <cuda_bf16.h>
#include <math.h>
#include <math_constants.h>
#include <stdint.h>

#define HIDDEN 2048
#define NH 16
#define NKV 4
#define HD 128
#define KVD 512
#define BATCH 2
#define SEQ 2048
#define M_TOT (BATCH * SEQ)   // 4096

// ---------------- scratch (no allocations allowed) ----------------
__device__ float g_q[M_TOT * HIDDEN];
__device__ float g_k[M_TOT * KVD];
__device__ float g_v[M_TOT * KVD];
__device__ float g_cos[SEQ * 64];
__device__ float g_sin[SEQ * 64];
// bf16 hi/lo split arrays
__device__ __nv_bfloat16 g_hsh[M_TOT * HIDDEN],  g_hsl[M_TOT * HIDDEN];
__device__ __nv_bfloat16 g_wqh[HIDDEN * HIDDEN], g_wql[HIDDEN * HIDDEN];
__device__ __nv_bfloat16 g_wkh[KVD * HIDDEN],    g_wkl[KVD * HIDDEN];
__device__ __nv_bfloat16 g_wvh[KVD * HIDDEN],    g_wvl[KVD * HIDDEN];
__device__ __nv_bfloat16 g_woh[HIDDEN * HIDDEN], g_wol[HIDDEN * HIDDEN];
__device__ __nv_bfloat16 g_qh[M_TOT * HIDDEN],   g_ql[M_TOT * HIDDEN];
__device__ __nv_bfloat16 g_kh[M_TOT * KVD],      g_kl[M_TOT * KVD];
__device__ __nv_bfloat16 g_vth[M_TOT * KVD],     g_vtl[M_TOT * KVD];  // [b][kvh][d][s]
__device__ __nv_bfloat16 g_ch[M_TOT * HIDDEN],   g_cl[M_TOT * HIDDEN];

// ---------------- helpers ----------------
__device__ __forceinline__ void split_bf16(float x, __nv_bfloat16& h, __nv_bfloat16& l) {
    h = __float2bfloat16_rn(x);
    l = __float2bfloat16_rn(x - __bfloat162float(h));
}
__device__ __forceinline__ uint32_t pack2(__nv_bfloat16 a, __nv_bfloat16 b) {
    __nv_bfloat162 t; t.x = a; t.y = b;   // low half = a (elem even)
    return *(uint32_t*)&t;
}
__device__ __forceinline__ void split4_pack(float4 v, uint2& ho, uint2& lo) {
    __nv_bfloat16 h0, l0, h1, l1, h2, l2, h3, l3;
    split_bf16(v.x, h0, l0); split_bf16(v.y, h1, l1);
    split_bf16(v.z, h2, l2); split_bf16(v.w, h3, l3);
    ho = make_uint2(pack2(h0, h1), pack2(h2, h3));
    lo = make_uint2(pack2(l0, l1), pack2(l2, l3));
}
__device__ __forceinline__ void mma_bf16(float c[4], const uint32_t a[4], const uint32_t b[2]) {
    asm volatile(
        "mma.sync.aligned.m16n8k16.row.col.f32.bf16.bf16.f32 "
        "{%0,%1,%2,%3}, {%4,%5,%6,%7}, {%8,%9}, {%0,%1,%2,%3};"
        : "+f"(c[0]), "+f"(c[1]), "+f"(c[2]), "+f"(c[3])
        : "r"(a[0]), "r"(a[1]), "r"(a[2]), "r"(a[3]), "r"(b[0]), "r"(b[1]));
}
#define CP_ASYNC16(sm32, gp) \
    asm volatile("cp.async.cg.shared.global [%0], [%1], 16;" :: "r"(sm32), "l"(gp))
#define CP_COMMIT() asm volatile("cp.async.commit_group;" ::: "memory")
#define CP_WAIT0()  asm volatile("cp.async.wait_group 0;" ::: "memory")
#define CP_WAIT1()  asm volatile("cp.async.wait_group 1;" ::: "memory")
#define CP_WAIT2()  asm volatile("cp.async.wait_group 2;" ::: "memory")

// ---------------- prep kernels (vectorized) ----------------
// fp32 exp2f + double range-reduction + fp32 trig (no fp64 libcalls)
__global__ void rope_table_kernel() {
    int i = blockIdx.x * blockDim.x + threadIdx.x;
    if (i >= SEQ * 64) return;
    int pos = i / 64, j = i % 64;
    // inv = 10000^(-2j/128); log2(10000) = 13.287712379549449
    float invf = exp2f(-(float)(2 * j) * (13.28771238f / 128.0f));
    double ang = (double)pos * (double)invf;
    double r = ang - floor(ang * 0.15915494309189535) * 6.283185307179586;
    float rf = (float)r;
    g_cos[i] = cosf(rf);
    g_sin[i] = sinf(rf);
}

// 4-wide split: float4 in, packed uint2 bf16 out (8B stores)
__global__ void split4_kernel(const float4* __restrict__ x,
                              uint2* __restrict__ h,
                              uint2* __restrict__ l, int n4) {
    int i = blockIdx.x * blockDim.x + threadIdx.x;
    if (i >= n4) return;
    uint2 ho, lo;
    split4_pack(x[i], ho, lo);
    h[i] = ho; l[i] = lo;
}

// RoPE + split, 4 j-lanes per thread (float4 loads, uint2 stores)
__global__ void rope_split4_kernel(const float* __restrict__ x,
                                   __nv_bfloat16* __restrict__ xh,
                                   __nv_bfloat16* __restrict__ xl,
                                   int nheads, int total16) {
    int i = blockIdx.x * blockDim.x + threadIdx.x;
    if (i >= total16) return;
    int jq = (i & 15) * 4;
    int hh = (i >> 4) % nheads;
    int m = i / (16 * nheads);
    int s = m % SEQ;
    size_t base = (size_t)m * (nheads * HD) + hh * HD;
    float4 x0 = *(const float4*)&x[base + jq];
    float4 x1 = *(const float4*)&x[base + jq + 64];
    float4 c  = *(const float4*)&g_cos[s * 64 + jq];
    float4 sn = *(const float4*)&g_sin[s * 64 + jq];
    float4 y0 = make_float4(x0.x * c.x - x1.x * sn.x, x0.y * c.y - x1.y * sn.y,
                            x0.z * c.z - x1.z * sn.z, x0.w * c.w - x1.w * sn.w);
    float4 y1 = make_float4(x1.x * c.x + x0.x * sn.x, x1.y * c.y + x0.y * sn.y,
                            x1.z * c.z + x0.z * sn.z, x1.w * c.w + x0.w * sn.w);
    uint2 ho, lo;
    split4_pack(y0, ho, lo);
    *(uint2*)&xh[base + jq] = ho; *(uint2*)&xl[base + jq] = lo;
    split4_pack(y1, ho, lo);
    *(uint2*)&xh[base + jq + 64] = ho; *(uint2*)&xl[base + jq + 64] = lo;
}

// V transpose + split: smem-tiled 32x32, both phases coalesced.
// in [b][s][kvh][d] fp32 -> out [b][kvh][d][s] bf16 hi/lo
__global__ void vt_split_kernel(const float* __restrict__ v) {
    __shared__ float tile[32][33];
    const int s0 = blockIdx.x * 32;
    const int d0 = blockIdx.y * 32;
    const int bk = blockIdx.z;            // b*NKV + kvh
    const int b = bk / NKV, kvh = bk % NKV;
    const int tx = threadIdx.x, ty = threadIdx.y;   // 32 x 8
#pragma unroll
    for (int r = 0; r < 4; r++) {
        int sl = ty * 4 + r;
        tile[sl][tx] = v[(size_t)(b * SEQ + s0 + sl) * KVD + kvh * HD + d0 + tx];
    }
    __syncthreads();
#pragma unroll
    for (int r = 0; r < 4; r++) {
        int dl = ty * 4 + r;
        size_t o = (((size_t)(b * NKV + kvh)) * HD + d0 + dl) * SEQ + s0 + tx;
        __nv_bfloat16 hb, lb;
        split_bf16(tile[tx][dl], hb, lb);
        g_vth[o] = hb; g_vtl[o] = lb;
    }
}

// ============ bf16-split tensor GEMM (NT): C = (Ah+Al)(Bh+Bl)^T ============
// A:[M][K], B:[N][K] hi/lo bf16. CTA tile 128x128, BK=32; 128 thr = 4 warps
// in 2(m) x 2(n), warp tile 64x64 (mt=4, nt=8). mma m16n8k16, 3 products
// (hh, hl, lh), fp32 accum. cp.async double-buffered.
#define GSA 20                       // row stride u32 (16 data + 4 pad): bank 4g+tig -> conflict-free
#define GTILE (128 * GSA)            // u32 per matrix tile
#define GBUF (4 * GTILE)             // Ah,Al,Bh,Bl
#define GEMM_SMEM (2 * GBUF * 4)     // double-buffered = 81920 B

__global__ void __launch_bounds__(128, 2) gemm_bf16_nt(
    const __nv_bfloat16* __restrict__ Ah, const __nv_bfloat16* __restrict__ Al,
    const __nv_bfloat16* __restrict__ Bh, const __nv_bfloat16* __restrict__ Bl,
    float* __restrict__ C, int Ndim, int Kdim)
{
    extern __shared__ uint32_t smu[];
    const int tid = threadIdx.x;
    const int wid = tid >> 5, lane = tid & 31;
    const int g = lane >> 2, tig = lane & 3;
    const int wm = wid & 1, wn = wid >> 1;     // 2x2 warp grid, 64x64 tiles
    const int bm0 = blockIdx.y * 128, bn0 = blockIdx.x * 128;
    const uint32_t smb = (uint32_t)__cvta_generic_to_shared(smu);
    const __nv_bfloat16* gp[4] = {Ah, Al, Bh, Bl};

    int rowL[4], q4L[4];
#pragma unroll
    for (int s = 0; s < 4; s++) {
        int f = tid + 128 * s;       // 0..511
        rowL[s] = f >> 2;
        q4L[s]  = f & 3;
    }

    float acc[4][8][4];
#pragma unroll
    for (int mt = 0; mt < 4; mt++)
#pragma unroll
        for (int nt = 0; nt < 8; nt++)
#pragma unroll
            for (int r = 0; r < 4; r++) acc[mt][nt][r] = 0.f;

    // prefetch tile 0 into buffer 0
#pragma unroll
    for (int mi = 0; mi < 4; mi++)
#pragma unroll
        for (int s = 0; s < 4; s++) {
            int row = rowL[s], q4 = q4L[s];
            int gbase = (mi < 2 ? bm0 : bn0);
            CP_ASYNC16(smb + (uint32_t)((mi * GTILE + row * GSA + q4 * 4) * 4),
                       gp[mi] + (size_t)(gbase + row) * Kdim + q4 * 8);
        }
    CP_COMMIT();

    int buf = 0;
    for (int k0 = 0; k0 < Kdim; k0 += 32) {
        CP_WAIT0();
        __syncthreads();

        if (k0 + 32 < Kdim) {
            uint32_t bb = smb + (uint32_t)(((buf ^ 1) * GBUF) * 4);
#pragma unroll
            for (int mi = 0; mi < 4; mi++)
#pragma unroll
                for (int s = 0; s < 4; s++) {
                    int row = rowL[s], q4 = q4L[s];
                    int gbase = (mi < 2 ? bm0 : bn0);
                    CP_ASYNC16(bb + (uint32_t)((mi * GTILE + row * GSA + q4 * 4) * 4),
                               gp[mi] + (size_t)(gbase + row) * Kdim + k0 + 32 + q4 * 8);
                }
        }
        CP_COMMIT();

        const uint32_t* Ash = smu + buf * GBUF;
        const uint32_t* Asl = Ash + GTILE;
        const uint32_t* Bsh = Ash + 2 * GTILE;
        const uint32_t* Bsl = Ash + 3 * GTILE;

#pragma unroll
        for (int ks = 0; ks < 2; ks++) {
            const int c = ks * 8 + tig;
            uint32_t ah[4][4], al[4][4];
#pragma unroll
            for (int mt = 0; mt < 4; mt++) {
                int row = wm * 64 + mt * 16 + g;
                ah[mt][0] = Ash[row * GSA + c];       ah[mt][1] = Ash[(row + 8) * GSA + c];
                ah[mt][2] = Ash[row * GSA + c + 4];   ah[mt][3] = Ash[(row + 8) * GSA + c + 4];
                al[mt][0] = Asl[row * GSA + c];       al[mt][1] = Asl[(row + 8) * GSA + c];
                al[mt][2] = Asl[row * GSA + c + 4];   al[mt][3] = Asl[(row + 8) * GSA + c + 4];
            }
#pragma unroll
            for (int nt = 0; nt < 8; nt++) {
                int n = wn * 64 + nt * 8 + g;
                uint32_t bh[2] = { Bsh[n * GSA + c], Bsh[n * GSA + c + 4] };
                uint32_t bl[2] = { Bsl[n * GSA + c], Bsl[n * GSA + c + 4] };
#pragma unroll
                for (int mt = 0; mt < 4; mt++) {
                    mma_bf16(acc[mt][nt], ah[mt], bh);
                    mma_bf16(acc[mt][nt], ah[mt], bl);
                    mma_bf16(acc[mt][nt], al[mt], bh);
                }
            }
        }
        buf ^= 1;
    }

#pragma unroll
    for (int mt = 0; mt < 4; mt++)
#pragma unroll
        for (int nt = 0; nt < 8; nt++) {
            int row = bm0 + wm * 64 + mt * 16 + g;
            int col = bn0 + wn * 64 + nt * 8 + 2 * tig;
            *(float2*)&C[(size_t)row * Ndim + col] =
                make_float2(acc[mt][nt][0], acc[mt][nt][1]);
            *(float2*)&C[(size_t)(row + 8) * Ndim + col] =
                make_float2(acc[mt][nt][2], acc[mt][nt][3]);
        }
}

// ============ bf16-split flash attention (causal, GQA) ============
// 128 q-rows per CTA, 64-wide kv tiles. 8 warps in 4(m) x 2(n):
// Scores warp tile 32x32 (mt=2, nt=4); PV warp tile 32x64 (mt=2, nt=8).
// K double-buffered cp.async; V^T deferred-wait; fp32 score staging
// aliased onto the consumed K buffer. P split to bf16 hi/lo in softmax.
#define FBM 128
#define FBN 64
#define QS 68   // u32 row stride (64 data + 4 pad): 4g+tig conflict-free
#define KS 68
#define VS 36   // 32 data + 4
#define PS 36
#define OQH 0
#define OQL 8704
#define OKH0 17408
#define OKL0 21760
#define OKH1 26112
#define OKL1 30464
#define OVTH 34816
#define OVTL 39424
#define OPH 44032
#define OPL 48640
#define OSROW 53248
#define OAMS 53376
#define FLASH_SMEM (53440 * 4)

__global__ void __launch_bounds__(256, 1) flash_bf16(const int* __restrict__ am) {
    extern __shared__ uint32_t smu[];
    float* srow = (float*)(smu + OSROW);
    int* ams = (int*)(smu + OAMS);

    const int tid = threadIdx.x;
    const int wid = tid >> 5, lane = tid & 31;
    const int g = lane >> 2, tig = lane & 3;
    const int wm = wid & 3, wn = wid >> 2;     // 4m x 2n
    const int qt = blockIdx.x, hh = blockIdx.y, b = blockIdx.z;
    const int q0 = qt * FBM;
    const int kvh = hh / (NH / NKV);
    const int tx = tid & 15, ty = tid >> 4;
    const uint32_t smb = (uint32_t)__cvta_generic_to_shared(smu);

    // ---- prologue: Q (hi+lo) + K(0) via cp.async, one group ----
    {
        const __nv_bfloat16* qhp = g_qh + ((size_t)(b * SEQ + q0) * HIDDEN + hh * HD);
        const __nv_bfloat16* qlp = g_ql + ((size_t)(b * SEQ + q0) * HIDDEN + hh * HD);
#pragma unroll
        for (int i = 0; i < 8; i++) {
            int c = tid + 256 * i, row = c >> 4, o = c & 15;
            CP_ASYNC16(smb + (uint32_t)((OQH + row * QS + o * 4) * 4), qhp + (size_t)row * HIDDEN + o * 8);
            CP_ASYNC16(smb + (uint32_t)((OQL + row * QS + o * 4) * 4), qlp + (size_t)row * HIDDEN + o * 8);
        }
        const __nv_bfloat16* khp = g_kh + ((size_t)(b * SEQ) * KVD + kvh * HD);
        const __nv_bfloat16* klp = g_kl + ((size_t)(b * SEQ) * KVD + kvh * HD);
#pragma unroll
        for (int i = 0; i < 4; i++) {
            int c = tid + 256 * i, row = c >> 4, o = c & 15;
            CP_ASYNC16(smb + (uint32_t)((OKH0 + row * KS + o * 4) * 4), khp + (size_t)row * KVD + o * 8);
            CP_ASYNC16(smb + (uint32_t)((OKL0 + row * KS + o * 4) * 4), klp + (size_t)row * KVD + o * 8);
        }
        CP_COMMIT();
    }

    float acc[2][8][4];     // PV accum: mt=2 (rows wm*32+mt*16+g,+8), nt=8 (d cols)
#pragma unroll
    for (int mt = 0; mt < 2; mt++)
#pragma unroll
        for (int nt = 0; nt < 8; nt++)
#pragma unroll
            for (int r = 0; r < 4; r++) acc[mt][nt][r] = 0.f;
    float mrow[8], lrow[8];
#pragma unroll
    for (int i = 0; i < 8; i++) { mrow[i] = -CUDART_INF_F; lrow[i] = 0.f; }

    const int nkt = q0 / FBN + 2;
    int buf = 0;
    for (int kt = 0; kt < nkt; kt++) {
        const int k0 = kt * FBN;
        __syncthreads();   // PV(t-1) done with VT/P; Sraw(t-1) consumed

        // V^T(t) group
        {
            const __nv_bfloat16* vhp = g_vth + ((size_t)(b * NKV + kvh) * HD) * SEQ;
            const __nv_bfloat16* vlp = g_vtl + ((size_t)(b * NKV + kvh) * HD) * SEQ;
#pragma unroll
            for (int i = 0; i < 4; i++) {
                int c = tid + 256 * i, d = c >> 3, o = c & 7;
                CP_ASYNC16(smb + (uint32_t)((OVTH + d * VS + o * 4) * 4), vhp + (size_t)d * SEQ + k0 + o * 8);
                CP_ASYNC16(smb + (uint32_t)((OVTL + d * VS + o * 4) * 4), vlp + (size_t)d * SEQ + k0 + o * 8);
            }
            CP_COMMIT();
        }
        // K(t+1) group into other buffer (committed even if empty)
        if (kt + 1 < nkt) {
            int okh = buf ? OKH0 : OKH1;
            int okl = buf ? OKL0 : OKL1;
            const __nv_bfloat16* khp = g_kh + ((size_t)(b * SEQ + k0 + FBN) * KVD + kvh * HD);
            const __nv_bfloat16* klp = g_kl + ((size_t)(b * SEQ + k0 + FBN) * KVD + kvh * HD);
#pragma unroll
            for (int i = 0; i < 4; i++) {
                int c = tid + 256 * i, row = c >> 4, o = c & 15;
                CP_ASYNC16(smb + (uint32_t)((okh + row * KS + o * 4) * 4), khp + (size_t)row * KVD + o * 8);
                CP_ASYNC16(smb + (uint32_t)((okl + row * KS + o * 4) * 4), klp + (size_t)row * KVD + o * 8);
            }
        }
        CP_COMMIT();

        if (tid < FBN) ams[tid] = am[b * SEQ + k0 + tid];

        CP_WAIT2();        // K(t) (and Q) complete
        __syncthreads();

        const uint32_t* Kh = smu + (buf ? OKH1 : OKH0);
        const uint32_t* Kl = smu + (buf ? OKL1 : OKL0);
        const uint32_t* Qh = smu + OQH;
        const uint32_t* Ql = smu + OQL;

        // ---- scores: S = (Qh+Ql)(Kh+Kl)^T, warp tile 32x32 ----
        float accs[2][4][4];
#pragma unroll
        for (int mt = 0; mt < 2; mt++)
#pragma unroll
            for (int nt = 0; nt < 4; nt++)
#pragma unroll
                for (int r = 0; r < 4; r++) accs[mt][nt][r] = 0.f;

#pragma unroll
        for (int ks = 0; ks < 8; ks++) {
            const int c = ks * 8 + tig;
            uint32_t ah[2][4], al[2][4];
#pragma unroll
            for (int mt = 0; mt < 2; mt++) {
                int row = wm * 32 + mt * 16 + g;
                ah[mt][0] = Qh[row * QS + c];     ah[mt][1] = Qh[(row + 8) * QS + c];
                ah[mt][2] = Qh[row * QS + c + 4]; ah[mt][3] = Qh[(row + 8) * QS + c + 4];
                al[mt][0] = Ql[row * QS + c];     al[mt][1] = Ql[(row + 8) * QS + c];
                al[mt][2] = Ql[row * QS + c + 4]; al[mt][3] = Ql[(row + 8) * QS + c + 4];
            }
#pragma unroll
            for (int nt = 0; nt < 4; nt++) {
                int n = wn * 32 + nt * 8 + g;
                uint32_t bh[2] = { Kh[n * KS + c], Kh[n * KS + c + 4] };
                uint32_t bl[2] = { Kl[n * KS + c], Kl[n * KS + c + 4] };
#pragma unroll
                for (int mt = 0; mt < 2; mt++) {
                    mma_bf16(accs[mt][nt], ah[mt], bh);
                    mma_bf16(accs[mt][nt], ah[mt], bl);
                    mma_bf16(accs[mt][nt], al[mt], bh);
                }
            }
        }
        __syncthreads();   // ALL warps done reading K(t) before aliasing

        // ---- stage raw scores fp32 into the consumed K buffer ----
        float* Sraw = (float*)(smu + (buf ? OKH1 : OKH0));   // [128][68]
#pragma unroll
        for (int mt = 0; mt < 2; mt++)
#pragma unroll
            for (int nt = 0; nt < 4; nt++) {
                int r0 = wm * 32 + mt * 16 + g;
                int c0 = wn * 32 + nt * 8 + 2 * tig;
                *(float2*)&Sraw[r0 * 68 + c0]       = make_float2(accs[mt][nt][0], accs[mt][nt][1]);
                *(float2*)&Sraw[(r0 + 8) * 68 + c0] = make_float2(accs[mt][nt][2], accs[mt][nt][3]);
            }
        __syncthreads();

        // ---- softmax: scale+mask, online rescale, write P hi/lo bf16 ----
        const float scale = 0.08838834764831845f;  // 1/sqrt(128)
#pragma unroll
        for (int i = 0; i < 8; i++) {
            int row = ty * 8 + i;
            int qglob = q0 + row;
            float4 s = *(float4*)&Sraw[row * 68 + tx * 4];
            float sv[4] = {s.x, s.y, s.z, s.w};
#pragma unroll
            for (int j = 0; j < 4; j++) {
                int kg = k0 + tx * 4 + j;
                float v = sv[j] * scale + ((ams[tx * 4 + j] == 0) ? -CUDART_INF_F : 0.f);
                if (kg > qglob) v = -CUDART_INF_F;
                sv[j] = v;
            }
            float mloc = fmaxf(fmaxf(sv[0], sv[1]), fmaxf(sv[2], sv[3]));
#pragma unroll
            for (int o = 8; o >= 1; o >>= 1)
                mloc = fmaxf(mloc, __shfl_xor_sync(0xffffffffu, mloc, o));
            float mnew = fmaxf(mrow[i], mloc);
            float alpha = __expf(mrow[i] - mnew);
            float p[4];
            float ls = 0.f;
#pragma unroll
            for (int j = 0; j < 4; j++) { p[j] = __expf(sv[j] - mnew); ls += p[j]; }
#pragma unroll
            for (int o = 8; o >= 1; o >>= 1)
                ls += __shfl_xor_sync(0xffffffffu, ls, o);
            lrow[i] = lrow[i] * alpha + ls;
            mrow[i] = mnew;
            __nv_bfloat16 h0, l0, h1, l1, h2, l2, h3, l3;
            split_bf16(p[0], h0, l0); split_bf16(p[1], h1, l1);
            split_bf16(p[2], h2, l2); split_bf16(p[3], h3, l3);
            smu[OPH + row * PS + 2 * tx]     = pack2(h0, h1);
            smu[OPH + row * PS + 2 * tx + 1] = pack2(h2, h3);
            smu[OPL + row * PS + 2 * tx]     = pack2(l0, l1);
            smu[OPL + row * PS + 2 * tx + 1] = pack2(l2, l3);
            if (tx == 0) srow[row] = alpha;
        }

        CP_WAIT1();        // V^T(t) complete (only K(t+1) may remain)
        __syncthreads();   // P, srow, V^T visible to all

        // ---- PV: acc = acc*alpha + (Ph+Pl)(Vh+Vl), warp tile 32x64 ----
#pragma unroll
        for (int mt = 0; mt < 2; mt++) {
            int r0 = wm * 32 + mt * 16 + g;
            float a0 = srow[r0], a1 = srow[r0 + 8];
#pragma unroll
            for (int nt = 0; nt < 8; nt++) {
                acc[mt][nt][0] *= a0; acc[mt][nt][1] *= a0;
                acc[mt][nt][2] *= a1; acc[mt][nt][3] *= a1;
            }
        }
        const uint32_t* Ph = smu + OPH;
        const uint32_t* Pl = smu + OPL;
        const uint32_t* Vh = smu + OVTH;
        const uint32_t* Vl = smu + OVTL;
#pragma unroll
        for (int ks = 0; ks < 4; ks++) {
            const int c = ks * 8 + tig;
            uint32_t ah[2][4], al[2][4];
#pragma unroll
            for (int mt = 0; mt < 2; mt++) {
                int row = wm * 32 + mt * 16 + g;
                ah[mt][0] = Ph[row * PS + c];     ah[mt][1] = Ph[(row + 8) * PS + c];
                ah[mt][2] = Ph[row * PS + c + 4]; ah[mt][3] = Ph[(row + 8) * PS + c + 4];
                al[mt][0] = Pl[row * PS + c];     al[mt][1] = Pl[(row + 8) * PS + c];
                al[mt][2] = Pl[row * PS + c + 4]; al[mt][3] = Pl[(row + 8) * PS + c + 4];
            }
#pragma unroll
            for (int nt = 0; nt < 8; nt++) {
                int d0 = wn * 64 + nt * 8 + g;
                uint32_t bh[2] = { Vh[d0 * VS + c], Vh[d0 * VS + c + 4] };
                uint32_t bl[2] = { Vl[d0 * VS + c], Vl[d0 * VS + c + 4] };
#pragma unroll
                for (int mt = 0; mt < 2; mt++) {
                    mma_bf16(acc[mt][nt], ah[mt], bh);
                    mma_bf16(acc[mt][nt], ah[mt], bl);
                    mma_bf16(acc[mt][nt], al[mt], bh);
                }
            }
        }
        buf ^= 1;
    }

    // ---- finalize: 1/l, write ctx hi/lo bf16 ----
    __syncthreads();
#pragma unroll
    for (int i = 0; i < 8; i++)
        if (tx == 0) srow[ty * 8 + i] = 1.0f / lrow[i];
    __syncthreads();

#pragma unroll
    for (int mt = 0; mt < 2; mt++) {
        int r0 = wm * 32 + mt * 16 + g;
        float inv0 = srow[r0], inv1 = srow[r0 + 8];
#pragma unroll
        for (int nt = 0; nt < 8; nt++) {
            int col = hh * HD + wn * 64 + nt * 8 + 2 * tig;
            size_t m0 = (size_t)(b * SEQ + q0 + r0) * HIDDEN + col;
            size_t m1 = (size_t)(b * SEQ + q0 + r0 + 8) * HIDDEN + col;
            __nv_bfloat16 h0, l0, h1, l1;
            split_bf16(acc[mt][nt][0] * inv0, h0, l0);
            split_bf16(acc[mt][nt][1] * inv0, h1, l1);
            *(uint32_t*)&g_ch[m0] = pack2(h0, h1);
            *(uint32_t*)&g_cl[m0] = pack2(l0, l1);
            split_bf16(acc[mt][nt][2] * inv1, h0, l0);
            split_bf16(acc[mt][nt][3] * inv1, h1, l1);
            *(uint32_t*)&g_ch[m1] = pack2(h0, h1);
            *(uint32_t*)&g_cl[m1] = pack2(l0, l1);
        }
    }
}

// ---------------- launch ----------------
extern "C" void kernel_launch(void* const* d_in, const int* in_sizes, int n_in,
                              void* d_out, int out_size) {
    (void)in_sizes; (void)n_in; (void)out_size;
    const float* hs = (const float*)d_in[0];
    const int*   am = (const int*)d_in[1];
    const float* wq = (const float*)d_in[2];
    const float* wk = (const float*)d_in[3];
    const float* wv = (const float*)d_in[4];
    const float* wo = (const float*)d_in[5];
    float* out = (float*)d_out;

    float *q, *k, *v;
    __nv_bfloat16 *hsh, *hsl, *wqh, *wql, *wkh, *wkl, *wvh, *wvl, *woh, *wol;
    __nv_bfloat16 *qh, *ql, *kh, *kl, *ch, *cl;
    cudaGetSymbolAddress((void**)&q, g_q);
    cudaGetSymbolAddress((void**)&k, g_k);
    cudaGetSymbolAddress((void**)&v, g_v);
    cudaGetSymbolAddress((void**)&hsh, g_hsh); cudaGetSymbolAddress((void**)&hsl, g_hsl);
    cudaGetSymbolAddress((void**)&wqh, g_wqh); cudaGetSymbolAddress((void**)&wql, g_wql);
    cudaGetSymbolAddress((void**)&wkh, g_wkh); cudaGetSymbolAddress((void**)&wkl, g_wkl);
    cudaGetSymbolAddress((void**)&wvh, g_wvh); cudaGetSymbolAddress((void**)&wvl, g_wvl);
    cudaGetSymbolAddress((void**)&woh, g_woh); cudaGetSymbolAddress((void**)&wol, g_wol);
    cudaGetSymbolAddress((void**)&qh, g_qh);   cudaGetSymbolAddress((void**)&ql, g_ql);
    cudaGetSymbolAddress((void**)&kh, g_kh);   cudaGetSymbolAddress((void**)&kl, g_kl);
    cudaGetSymbolAddress((void**)&ch, g_ch);   cudaGetSymbolAddress((void**)&cl, g_cl);

    cudaFuncSetAttribute(gemm_bf16_nt,
                         cudaFuncAttributeMaxDynamicSharedMemorySize, GEMM_SMEM);
    cudaFuncSetAttribute(flash_bf16,
                         cudaFuncAttributeMaxDynamicSharedMemorySize, FLASH_SMEM);

    // splits first (vectorized); launch index 5 is then the Q-proj GEMM,
    // which is what ncu (-s 5 -c 1) will capture next round.
    split4_kernel<<<(M_TOT * HIDDEN / 4 + 255) / 256, 256>>>((const float4*)hs, (uint2*)hsh, (uint2*)hsl, M_TOT * HIDDEN / 4);
    split4_kernel<<<(HIDDEN * HIDDEN / 4 + 255) / 256, 256>>>((const float4*)wq, (uint2*)wqh, (uint2*)wql, HIDDEN * HIDDEN / 4);
    split4_kernel<<<(KVD * HIDDEN / 4 + 255) / 256, 256>>>((const float4*)wk, (uint2*)wkh, (uint2*)wkl, KVD * HIDDEN / 4);
    split4_kernel<<<(KVD * HIDDEN / 4 + 255) / 256, 256>>>((const float4*)wv, (uint2*)wvh, (uint2*)wvl, KVD * HIDDEN / 4);
    split4_kernel<<<(HIDDEN * HIDDEN / 4 + 255) / 256, 256>>>((const float4*)wo, (uint2*)woh, (uint2*)wol, HIDDEN * HIDDEN / 4);

    // projections (4-warp, 64x64 warp-tile GEMM)
    gemm_bf16_nt<<<dim3(HIDDEN / 128, M_TOT / 128), 128, GEMM_SMEM>>>(hsh, hsl, wqh, wql, q, HIDDEN, HIDDEN);
    gemm_bf16_nt<<<dim3(KVD / 128,   M_TOT / 128), 128, GEMM_SMEM>>>(hsh, hsl, wkh, wkl, k, KVD, HIDDEN);
    gemm_bf16_nt<<<dim3(KVD / 128,   M_TOT / 128), 128, GEMM_SMEM>>>(hsh, hsl, wvh, wvl, v, KVD, HIDDEN);

    // rope table (needed only before rope_split) + vectorized rope/transpose splits
    rope_table_kernel<<<(SEQ * 64 + 255) / 256, 256>>>();
    rope_split4_kernel<<<(M_TOT * NH * 16 + 255) / 256, 256>>>(q, qh, ql, NH, M_TOT * NH * 16);
    rope_split4_kernel<<<(M_TOT * NKV * 16 + 255) / 256, 256>>>(k, kh, kl, NKV, M_TOT * NKV * 16);
    vt_split_kernel<<<dim3(SEQ / 32, HD / 32, BATCH * NKV), dim3(32, 8)>>>(v);

    // attention
    flash_bf16<<<dim3(SEQ / FBM, NH, BATCH), 256, FLASH_SMEM>>>(am);

    // output projection
    gemm_bf16_nt<<<dim3(HIDDEN / 128, M_TOT / 128), 128, GEMM_SMEM>>>(ch, cl, woh, wol, out, HIDDEN, HIDDEN);
}